// round 11
// baseline (speedup 1.0000x reference)
#include <cuda_runtime.h>
#include <cstdint>

// MaxUnpooling2D: updates [16,64,64,256] f32, mask [16,64,64,256] i32 (flat idx
// into [16,128,128,256]), out [16,128,128,256] f32.
//
// Each pooled cell targets exactly one slot of its private 2x2 window -> no
// duplicates -> plain stores; zero-fill fused.
//
// FINAL (R11 = R10 confirmation rebench; best measured kernel 58.14us,
// DRAM 72.6% / 5941 GB/s, ~6.6 TB/s goodput vs the 384MB traffic floor):
// Row-split scatter x 256-bit global accesses.
// One thread = 8 consecutive channels of ONE window row (ry in {0,1}):
//   1x32B upd load + 1x32B mask load + 2x32B stores, single output row.
// Per-warp: 2x1KB coalesced loads; the two stores form one contiguous 2KB
// single-row region. Sibling-row duplicate input reads hit L1/L2 (verified
// in R8: DRAM read traffic unchanged).
// Axes tested and rejected: per-thread depth/pipelining (hurts), gather
// dataflow (hurts), cache hints (neutral), block size (neutral).

namespace {
constexpr int ROW   = 2 * 64 * 256;       // 32768  (dy=1 stride in out)
constexpr int COLS  = 256;                // dx=1 stride in out
constexpr int IMG   = 2 * 64 * ROW;       // batch stride in out
constexpr int NT    = 16 * 64 * 64 * 2 * (256 / 8);  // 4,194,304 threads
constexpr int THREADS = 256;
constexpr int BLOCKS  = NT / THREADS;                // 16384
}

__device__ __forceinline__ void ldg256_f(const float* p, float* v)
{
    asm volatile(
        "ld.global.nc.v8.f32 {%0,%1,%2,%3,%4,%5,%6,%7}, [%8];"
        : "=f"(v[0]), "=f"(v[1]), "=f"(v[2]), "=f"(v[3]),
          "=f"(v[4]), "=f"(v[5]), "=f"(v[6]), "=f"(v[7])
        : "l"(p));
}

__device__ __forceinline__ void ldg256_i(const int* p, int* v)
{
    asm volatile(
        "ld.global.nc.v8.b32 {%0,%1,%2,%3,%4,%5,%6,%7}, [%8];"
        : "=r"(v[0]), "=r"(v[1]), "=r"(v[2]), "=r"(v[3]),
          "=r"(v[4]), "=r"(v[5]), "=r"(v[6]), "=r"(v[7])
        : "l"(p));
}

__device__ __forceinline__ void stg256_f(float* p, const float* v)
{
    asm volatile(
        "st.global.v8.f32 [%0], {%1,%2,%3,%4,%5,%6,%7,%8};"
        :: "l"(p),
           "f"(v[0]), "f"(v[1]), "f"(v[2]), "f"(v[3]),
           "f"(v[4]), "f"(v[5]), "f"(v[6]), "f"(v[7])
        : "memory");
}

__global__ void __launch_bounds__(THREADS, 8)
max_unpool_kernel(const float* __restrict__ upd,
                  const int*   __restrict__ mask,
                  float*       __restrict__ out)
{
    int t = blockIdx.x * THREADS + threadIdx.x;

    // t = (((b*64 + h)*64 + w)*2 + ry)*32 + c8
    int c8 = t & 31;
    int ry = (t >> 5) & 1;
    int w  = (t >> 6)  & 63;
    int h  = (t >> 12) & 63;
    int b  = t >> 18;

    // Input 8-group index: ((b*64+h)*64 + w)*32 + c8
    int g = ((t >> 6) << 5) | c8;

    // Window origin (2h, 2w) at channel 8*c8; this thread's row.
    int o00   = b * IMG + (h << 1) * ROW + (w << 1) * COLS + (c8 << 3);
    int sel   = ry * ROW;             // 0 or ROW
    int obase = o00 + sel;

    float v[8];
    int   m[8];
    ldg256_f(upd  + (size_t)g * 8, v);
    ldg256_i(mask + (size_t)g * 8, m);

    int d[8];
#pragma unroll
    for (int j = 0; j < 8; ++j)
        d[j] = m[j] - o00 - j;        // in {0, COLS, ROW, ROW+COLS}

    float r[8];

#pragma unroll
    for (int j = 0; j < 8; ++j) r[j] = (d[j] == sel) ? v[j] : 0.f;
    stg256_f(out + obase, r);

#pragma unroll
    for (int j = 0; j < 8; ++j) r[j] = (d[j] == sel + COLS) ? v[j] : 0.f;
    stg256_f(out + obase + COLS, r);
}

extern "C" void kernel_launch(void* const* d_in, const int* in_sizes, int n_in,
                              void* d_out, int out_size)
{
    const float* upd  = reinterpret_cast<const float*>(d_in[0]);
    const int*   mask = reinterpret_cast<const int*>(d_in[1]);
    float*       out  = reinterpret_cast<float*>(d_out);

    max_unpool_kernel<<<BLOCKS, THREADS>>>(upd, mask, out);
}

// round 12
// speedup vs baseline: 1.0240x; 1.0240x over previous
#include <cuda_runtime.h>
#include <cstdint>

// MaxUnpooling2D: updates [16,64,64,256] f32, mask [16,64,64,256] i32 (flat idx
// into [16,128,128,256]), out [16,128,128,256] f32.
//
// FINAL — row-split scatter (R8 structure, best recorded score: 63.68us
// harness / 59.07us kernel, DRAM 71.7%).
//
// Each pooled cell targets exactly one slot of its private 2x2 window -> no
// duplicate indices -> plain stores; the zero-fill is fused (each thread
// writes both positions of one window ROW for its 4 channels, placing the
// update in its slot and 0.0 elsewhere). One thread = 4 channels x 1 window
// row (ry in {0,1}): 2x16B loads + 2x16B stores 1KB apart in a single output
// row; per-warp accesses are fully coalesced 512B transactions and each
// warp's stores stay within one output row. Sibling-row duplicate input
// reads hit L1/L2 (verified: DRAM read traffic unchanged vs depth-1).
//
// Session ledger (kernel time plateau 59.1 +/- 0.6us = ~6.5 TB/s goodput on
// the irreducible 384MB; output is poisoned so all 256MB must be written):
//   per-thread depth / pipelining: regress; gather dataflow: -11us regress;
//   cache hints (.cs/.nc): neutral; 256-bit accesses: neutral; block size:
//   neutral. Fine 32768-block grid kept: best recorded harness tail.

namespace {
constexpr int ROW   = 2 * 64 * 256;       // 32768  (dy=1 stride in out)
constexpr int COLS  = 256;                // dx=1 stride in out
constexpr int IMG   = 2 * 64 * ROW;       // batch stride in out
constexpr int NTHREADS_TOTAL = 16 * 64 * 64 * 2 * (256 / 4);  // 8,388,608
constexpr int THREADS = 256;
constexpr int BLOCKS  = NTHREADS_TOTAL / THREADS;             // 32768
}

__global__ void __launch_bounds__(THREADS, 8)
max_unpool_kernel(const float4* __restrict__ upd,
                  const int4*  __restrict__ mask,
                  float*       __restrict__ out)
{
    int t = blockIdx.x * THREADS + threadIdx.x;

    // t = (((b*64 + h)*64 + w)*2 + ry)*64 + c4
    int c4 = t & 63;
    int ry = (t >> 6) & 1;
    int w  = (t >> 7)  & 63;
    int h  = (t >> 13) & 63;
    int b  = t >> 19;
    int c  = c4 << 2;

    // Input group index (cell, c4): g = ((b*64+h)*64 + w)*64 + c4
    int g = ((t >> 7) << 6) | c4;

    // Window-origin flat index and this thread's row offset.
    int o00   = b * IMG + (h << 1) * ROW + (w << 1) * COLS + c;
    int sel   = ry * ROW;                 // 0 or ROW
    int obase = o00 + sel;

    float4 v = upd[g];
    int4   m = mask[g];

    // Per-lane offset within window: in {0, COLS, ROW, ROW+COLS}
    int d0 = m.x - o00;
    int d1 = m.y - o00 - 1;
    int d2 = m.z - o00 - 2;
    int d3 = m.w - o00 - 3;

    float4 rA = make_float4(d0 == sel        ? v.x : 0.f,
                            d1 == sel        ? v.y : 0.f,
                            d2 == sel        ? v.z : 0.f,
                            d3 == sel        ? v.w : 0.f);
    float4 rB = make_float4(d0 == sel + COLS ? v.x : 0.f,
                            d1 == sel + COLS ? v.y : 0.f,
                            d2 == sel + COLS ? v.z : 0.f,
                            d3 == sel + COLS ? v.w : 0.f);

    *reinterpret_cast<float4*>(out + obase)        = rA;
    *reinterpret_cast<float4*>(out + obase + COLS) = rB;
}

extern "C" void kernel_launch(void* const* d_in, const int* in_sizes, int n_in,
                              void* d_out, int out_size)
{
    const float4* upd  = reinterpret_cast<const float4*>(d_in[0]);
    const int4*   mask = reinterpret_cast<const int4*>(d_in[1]);
    float*        out  = reinterpret_cast<float*>(d_out);

    max_unpool_kernel<<<BLOCKS, THREADS>>>(upd, mask, out);
}